// round 11
// baseline (speedup 1.0000x reference)
#include <cuda_runtime.h>
#include <cuda_bf16.h>
#include <mma.h>
#include <cstdint>

using namespace nvcuda;

#define NNODES 100000
#define NEDGES 1600000
#define HID 128
#define NGRAPH 64
#define SCAN_BLK 1024
#define EPW 16           // edges per warp (two batches of 8)

// ---------------- scratch (device globals) -----------------------------------
__device__ uint2  g_ybf[NNODES * 32];          // y in bf16: 128 bf16/row = 32 uint2
__device__ float4 g_bufB4[NNODES * HID / 4];   // agg layer 1
__device__ float4 g_bufC4[NNODES * HID / 4];   // agg layer 2
__device__ int    g_indeg[NNODES];
__device__ int    g_btot[128];
__device__ int    g_btop[128];
__device__ int    g_cursor[NNODES];
__device__ int2   g_edges[NEDGES];             // (src,dst) sorted by dst
__device__ float  g_stats[4 * HID];            // layer1: [0,256), layer2: [256,512)
__device__ float  g_scsh[2 * HID];
__device__ float  g_pooled[NGRAPH * HID];
__device__ float  g_counts[NGRAPH];

// ---------------- fused zero init ---------------------------------------------
__global__ void zero_all(int* indeg, float* stats, float* pooled, float* counts, int n) {
    int i = blockIdx.x * blockDim.x + threadIdx.x;
    if (i < n) indeg[i] = 0;
    if (i < 4 * HID) stats[i] = 0.f;
    if (i < NGRAPH * HID) pooled[i] = 0.f;
    if (i < NGRAPH) counts[i] = 0.f;
}

__global__ void indeg_count(const int* __restrict__ dst, int* indeg, int E) {
    int e = blockIdx.x * blockDim.x + threadIdx.x;
    if (e < E) atomicAdd(&indeg[dst[e]], 1);
}

__global__ void block_totals(const int* __restrict__ indeg, int* btot, int n) {
    __shared__ int sh[SCAN_BLK];
    int i = blockIdx.x * SCAN_BLK + threadIdx.x;
    sh[threadIdx.x] = (i < n) ? indeg[i] : 0;
    __syncthreads();
    for (int s = SCAN_BLK / 2; s > 0; s >>= 1) {
        if (threadIdx.x < s) sh[threadIdx.x] += sh[threadIdx.x + s];
        __syncthreads();
    }
    if (threadIdx.x == 0) btot[blockIdx.x] = sh[0];
}

__global__ void scan_tops(const int* __restrict__ btot, int* btop, int nb) {
    if (threadIdx.x == 0) {
        int acc = 0;
        for (int b = 0; b < nb; b++) { btop[b] = acc; acc += btot[b]; }
    }
}

__global__ void scan_blocks(const int* __restrict__ indeg, const int* __restrict__ btop,
                            int* cursor, int n) {
    __shared__ int sh[SCAN_BLK];
    int tid = threadIdx.x;
    int i = blockIdx.x * SCAN_BLK + tid;
    int v = (i < n) ? indeg[i] : 0;
    sh[tid] = v;
    __syncthreads();
    for (int off = 1; off < SCAN_BLK; off <<= 1) {
        int t = (tid >= off) ? sh[tid - off] : 0;
        __syncthreads();
        sh[tid] += t;
        __syncthreads();
    }
    if (i < n) cursor[i] = btop[blockIdx.x] + sh[tid] - v;  // exclusive prefix
}

__global__ void sort_fill(const int* __restrict__ src, const int* __restrict__ dst,
                          int* cursor, int2* edges, int E) {
    int e = blockIdx.x * blockDim.x + threadIdx.x;
    if (e < E) {
        int d = dst[e];
        int pos = atomicAdd(&cursor[d], 1);
        edges[pos] = make_int2(src[e], d);
    }
}

// ---------------- fused GEMM (tf32 tensor cores) --------------------------------
// ybf[row] = bf16((f(A)[row] @ W) * dinv)   — scatter input
// agg[row] = (f(A)@W) * dinv * dinv  fp32   — self-loop term
// f = nan_to_num (mode 1) / BN+ReLU via scsh (mode 2)
// 8 warps: warp = 4 row-blocks (16 rows) x 2 col-blocks (64 cols), wmma m16n16k8.
__global__ __launch_bounds__(256) void gemm128(
    const float* __restrict__ A, const float* __restrict__ W,
    const float* __restrict__ scsh, const int* __restrict__ indeg,
    uint2* __restrict__ ybf, float* __restrict__ agg, int n, int mode)
{
    __shared__ __align__(16) float smem[64 * 128];   // 32KB; As/Ws alias, Cs reuses
    float* As = smem;              // 64 x 32
    float* Ws = smem + 64 * 32;    // 32 x 128

    int r0 = blockIdx.x * 64;
    int tid = threadIdx.x;
    int warp = tid >> 5;
    int row_blk = warp & 3;        // x16 rows
    int col_blk = warp >> 2;       // x64 cols

    wmma::fragment<wmma::accumulator, 16, 16, 8, float> acc[4];
    #pragma unroll
    for (int c = 0; c < 4; c++) wmma::fill_fragment(acc[c], 0.f);

    for (int kc = 0; kc < 4; kc++) {
        // A tile 64x32 with transform, converted to tf32
        #pragma unroll
        for (int t = 0; t < 2; t++) {
            int i = tid + t * 256;
            int r = i >> 3;
            int k4 = (i & 7) * 4;
            float4 v = make_float4(0.f, 0.f, 0.f, 0.f);
            if (r0 + r < n)
                v = *(const float4*)(A + (size_t)(r0 + r) * 128 + kc * 32 + k4);
            if (mode == 1) {
                v.x = (v.x == v.x) ? v.x : 0.f;
                v.y = (v.y == v.y) ? v.y : 0.f;
                v.z = (v.z == v.z) ? v.z : 0.f;
                v.w = (v.w == v.w) ? v.w : 0.f;
            } else if (mode == 2) {
                int c = kc * 32 + k4;
                v.x = fmaxf(v.x * scsh[c + 0] + scsh[128 + c + 0], 0.f);
                v.y = fmaxf(v.y * scsh[c + 1] + scsh[128 + c + 1], 0.f);
                v.z = fmaxf(v.z * scsh[c + 2] + scsh[128 + c + 2], 0.f);
                v.w = fmaxf(v.w * scsh[c + 3] + scsh[128 + c + 3], 0.f);
            }
            v.x = wmma::__float_to_tf32(v.x);
            v.y = wmma::__float_to_tf32(v.y);
            v.z = wmma::__float_to_tf32(v.z);
            v.w = wmma::__float_to_tf32(v.w);
            *(float4*)(As + r * 32 + k4) = v;
        }
        // W tile 32x128, converted to tf32
        #pragma unroll
        for (int t = 0; t < 4; t++) {
            int i = tid + t * 256;
            int k = i >> 5, c4 = (i & 31) * 4;
            float4 w = *(const float4*)(W + (size_t)(kc * 32 + k) * 128 + c4);
            w.x = wmma::__float_to_tf32(w.x);
            w.y = wmma::__float_to_tf32(w.y);
            w.z = wmma::__float_to_tf32(w.z);
            w.w = wmma::__float_to_tf32(w.w);
            *(float4*)(Ws + k * 128 + c4) = w;
        }
        __syncthreads();

        #pragma unroll
        for (int kk = 0; kk < 4; kk++) {
            wmma::fragment<wmma::matrix_a, 16, 16, 8, wmma::precision::tf32, wmma::row_major> af;
            wmma::load_matrix_sync(af, As + (row_blk * 16) * 32 + kk * 8, 32);
            #pragma unroll
            for (int c = 0; c < 4; c++) {
                wmma::fragment<wmma::matrix_b, 16, 16, 8, wmma::precision::tf32, wmma::row_major> bf;
                wmma::load_matrix_sync(bf, Ws + (kk * 8) * 128 + col_blk * 64 + c * 16, 128);
                wmma::mma_sync(acc[c], af, bf, acc[c]);
            }
        }
        __syncthreads();
    }

    // stash accumulators into smem (As/Ws dead now)
    #pragma unroll
    for (int c = 0; c < 4; c++)
        wmma::store_matrix_sync(smem + (row_blk * 16) * 128 + col_blk * 64 + c * 16,
                                acc[c], 128, wmma::mem_row_major);
    __syncthreads();

    // epilogue: identical output path as before
    int cg = tid & 31;
    int rg = tid >> 5;
    #pragma unroll
    for (int r = 0; r < 8; r++) {
        int row = r0 + rg * 8 + r;
        if (row < n) {
            float di = rsqrtf((float)indeg[row] + 1.0f);
            float4 v = *(float4*)(smem + (rg * 8 + r) * 128 + cg * 4);
            v.x *= di; v.y *= di; v.z *= di; v.w *= di;
            __nv_bfloat162 h0 = __floats2bfloat162_rn(v.x, v.y);
            __nv_bfloat162 h1 = __floats2bfloat162_rn(v.z, v.w);
            uint2 u;
            u.x = *(unsigned int*)&h0;
            u.y = *(unsigned int*)&h1;
            ybf[(size_t)row * 32 + cg] = u;
            float4 s = make_float4(v.x * di, v.y * di, v.z * di, v.w * di);
            *(float4*)(agg + (size_t)row * 128 + cg * 4) = s;
        }
    }
}

// ---------------- sorted edge scatter (bf16 reads, fp32 accumulate) ------------
__device__ __forceinline__ void red_flush(float* agg, const int* indeg,
                                          int node, int lane, float4 a)
{
    float c = rsqrtf((float)__ldg(indeg + node) + 1.0f);
    float* p = agg + (size_t)node * 128 + lane * 4;
    asm volatile("red.global.add.v4.f32 [%0], {%1, %2, %3, %4};"
                 :: "l"(p), "f"(a.x * c), "f"(a.y * c), "f"(a.z * c), "f"(a.w * c)
                 : "memory");
}

__device__ __forceinline__ float4 unpack_bf16x4(uint2 u) {
    __nv_bfloat162 h0 = *(__nv_bfloat162*)&u.x;
    __nv_bfloat162 h1 = *(__nv_bfloat162*)&u.y;
    float2 a = __bfloat1622float2(h0);
    float2 b = __bfloat1622float2(h1);
    return make_float4(a.x, a.y, b.x, b.y);
}

__global__ __launch_bounds__(256) void edge_scatter_sorted(
    const uint2* __restrict__ ybf, const int2* __restrict__ edges,
    const int* __restrict__ indeg, float* __restrict__ agg, int E)
{
    int lane = threadIdx.x & 31;
    int warp = blockIdx.x * 8 + (threadIdx.x >> 5);
    int e0 = warp * EPW;
    if (e0 >= E) return;

    if (e0 + EPW <= E) {
        float4 acc = make_float4(0.f, 0.f, 0.f, 0.f);
        int cur = -1;
        #pragma unroll
        for (int b = 0; b < EPW / 8; b++) {
            int2 ed[8];
            #pragma unroll
            for (int j = 0; j < 8; j++)
                ed[j] = __ldg(edges + e0 + b * 8 + j);
            uint2 raw[8];
            #pragma unroll
            for (int j = 0; j < 8; j++)
                raw[j] = __ldg(ybf + (size_t)ed[j].x * 32 + lane);
            #pragma unroll
            for (int j = 0; j < 8; j++) {
                float4 v = unpack_bf16x4(raw[j]);
                if (ed[j].y == cur) {              // warp-uniform branch
                    acc.x += v.x; acc.y += v.y;
                    acc.z += v.z; acc.w += v.w;
                } else {
                    if (cur >= 0) red_flush(agg, indeg, cur, lane, acc);
                    cur = ed[j].y;
                    acc = v;
                }
            }
        }
        red_flush(agg, indeg, cur, lane, acc);
    } else {
        for (int e = e0; e < E; e++) {
            int2 ed = __ldg(edges + e);
            float4 v = unpack_bf16x4(__ldg(ybf + (size_t)ed.x * 32 + lane));
            red_flush(agg, indeg, ed.y, lane, v);
        }
    }
}

// ---------------- batchnorm -----------------------------------------------------
__global__ __launch_bounds__(128) void bn_stats(
    const float* __restrict__ src, float* __restrict__ stats, int n)
{
    int col = threadIdx.x;
    float s = 0.f, s2 = 0.f;
    for (int r = blockIdx.x; r < n; r += gridDim.x) {
        float v = src[(size_t)r * 128 + col];
        s += v; s2 += v * v;
    }
    atomicAdd(&stats[col], s);
    atomicAdd(&stats[128 + col], s2);
}

__global__ void bn_finalize(
    const float* __restrict__ stats, const float* __restrict__ gamma,
    const float* __restrict__ beta, float* __restrict__ scsh, int n)
{
    int c = threadIdx.x;  // 128 threads
    float invn = 1.0f / (float)n;
    float mean = stats[c] * invn;
    float var  = stats[128 + c] * invn - mean * mean;
    float sc = rsqrtf(var + 1e-5f) * gamma[c];
    scsh[c] = sc;
    scsh[128 + c] = beta[c] - mean * sc;
}

// ---------------- pooling (BN+ReLU fused; batch sorted) --------------------------
__global__ __launch_bounds__(256) void counts_kernel(
    const int* __restrict__ batch, float* __restrict__ counts, int n)
{
    __shared__ float sc[NGRAPH];
    if (threadIdx.x < NGRAPH) sc[threadIdx.x] = 0.f;
    __syncthreads();
    for (int i = blockIdx.x * blockDim.x + threadIdx.x; i < n; i += gridDim.x * blockDim.x)
        atomicAdd(&sc[batch[i]], 1.0f);
    __syncthreads();
    if (threadIdx.x < NGRAPH) atomicAdd(&counts[threadIdx.x], sc[threadIdx.x]);
}

__global__ __launch_bounds__(128) void pool_kernel(
    const float* __restrict__ agg, const float* __restrict__ scsh,
    const int* __restrict__ batch, float* __restrict__ pooled, int n)
{
    int col = threadIdx.x;
    float sc = scsh[col], sh = scsh[128 + col];
    int r0 = blockIdx.x * 128;
    if (r0 >= n) return;
    int r1 = min(r0 + 128, n);
    int cg = batch[r0];
    float acc = 0.f;
    for (int r = r0; r < r1; r++) {
        int g = batch[r];
        if (g != cg) {
            atomicAdd(&pooled[cg * 128 + col], acc);
            acc = 0.f;
            cg = g;
        }
        acc += fmaxf(agg[(size_t)r * 128 + col] * sc + sh, 0.f);
    }
    atomicAdd(&pooled[cg * 128 + col], acc);
}

// ---------------- classifier (single block) --------------------------------------
__global__ __launch_bounds__(256) void classifier_kernel(
    const float* __restrict__ pooled, const float* __restrict__ counts,
    const float* __restrict__ Wc1, const float* __restrict__ bc1,
    const float* __restrict__ Wc2, const float* __restrict__ bc2,
    float* __restrict__ out)
{
    __shared__ float Z[64 * 64];
    __shared__ float inv[NGRAPH];
    int tid = threadIdx.x;
    if (tid < NGRAPH) inv[tid] = 1.0f / fmaxf(counts[tid], 1.0f);
    __syncthreads();

    for (int idx = tid; idx < 64 * 64; idx += 256) {
        int r = idx >> 6, c = idx & 63;
        float dot = 0.f;
        #pragma unroll 8
        for (int k = 0; k < 128; k++)
            dot += pooled[r * 128 + k] * Wc1[k * 64 + c];
        Z[idx] = fmaxf(dot * inv[r] + bc1[c], 0.f);
    }
    __syncthreads();

    for (int idx = tid; idx < 128; idx += 256) {
        int r = idx >> 1, c = idx & 1;
        float dot = bc2[c];
        #pragma unroll
        for (int k = 0; k < 64; k++)
            dot += Z[r * 64 + k] * Wc2[k * 2 + c];
        out[idx] = (dot == dot) ? dot : 0.f;  // nan_to_num
    }
}

// ---------------- launch -----------------------------------------------------------
extern "C" void kernel_launch(void* const* d_in, const int* in_sizes, int n_in,
                              void* d_out, int out_size)
{
    const float* x     = (const float*)d_in[0];
    const int*   ei    = (const int*)d_in[1];
    const int*   batch = (const int*)d_in[2];
    const float* W1  = (const float*)d_in[3];
    // b1 = d_in[4] — exactly cancelled by BatchNorm
    const float* g1  = (const float*)d_in[5];
    const float* be1 = (const float*)d_in[6];
    const float* W2  = (const float*)d_in[7];
    // b2 = d_in[8] — same
    const float* g2  = (const float*)d_in[9];
    const float* be2 = (const float*)d_in[10];
    const float* Wc1 = (const float*)d_in[11];
    const float* bc1 = (const float*)d_in[12];
    const float* Wc2 = (const float*)d_in[13];
    const float* bc2 = (const float*)d_in[14];
    float* out = (float*)d_out;

    int n = in_sizes[0] / HID;
    int E = in_sizes[1] / 2;
    const int* srcp = ei;
    const int* dstp = ei + E;

    float *bufB, *bufC, *stats, *scsh, *pooled, *counts;
    int *indeg, *btot, *btop, *cursor;
    int2 *edges;
    uint2 *ybf;
    cudaGetSymbolAddress((void**)&ybf,    g_ybf);
    cudaGetSymbolAddress((void**)&bufB,   g_bufB4);
    cudaGetSymbolAddress((void**)&bufC,   g_bufC4);
    cudaGetSymbolAddress((void**)&indeg,  g_indeg);
    cudaGetSymbolAddress((void**)&btot,   g_btot);
    cudaGetSymbolAddress((void**)&btop,   g_btop);
    cudaGetSymbolAddress((void**)&cursor, g_cursor);
    cudaGetSymbolAddress((void**)&edges,  g_edges);
    cudaGetSymbolAddress((void**)&stats,  g_stats);
    cudaGetSymbolAddress((void**)&scsh,   g_scsh);
    cudaGetSymbolAddress((void**)&pooled, g_pooled);
    cudaGetSymbolAddress((void**)&counts, g_counts);

    int nb256 = (n + 255) / 256;
    int eb256 = (E + 255) / 256;
    int gemm_blocks = (n + 63) / 64;
    int scan_nb = (n + SCAN_BLK - 1) / SCAN_BLK;
    int scat_blocks = (E + 8 * EPW - 1) / (8 * EPW);

    // (1) fused zero init; (2) degree count; (3) scan part 1
    zero_all<<<nb256, 256>>>(indeg, stats, pooled, counts, n);
    indeg_count<<<eb256, 256>>>(dstp, indeg, E);
    block_totals<<<scan_nb, SCAN_BLK>>>(indeg, btot, n);

    // (4) layer-1 GEMM — the launch ncu captures
    gemm128<<<gemm_blocks, 256>>>(x, W1, scsh, indeg, ybf, bufB, n, 1);

    // (5)(6)(7) finish dst-sorted edge list before scatter
    scan_tops<<<1, 32>>>(btot, btop, scan_nb);
    scan_blocks<<<scan_nb, SCAN_BLK>>>(indeg, btop, cursor, n);
    sort_fill<<<eb256, 256>>>(srcp, dstp, cursor, edges, E);

    // ---- layer 1 aggregation + BN ----
    edge_scatter_sorted<<<scat_blocks, 256>>>(ybf, edges, indeg, bufB, E);
    bn_stats<<<512, 128>>>(bufB, stats, n);
    bn_finalize<<<1, 128>>>(stats, g1, be1, scsh, n);

    // ---- layer 2 ----
    gemm128<<<gemm_blocks, 256>>>(bufB, W2, scsh, indeg, ybf, bufC, n, 2);
    edge_scatter_sorted<<<scat_blocks, 256>>>(ybf, edges, indeg, bufC, E);
    bn_stats<<<512, 128>>>(bufC, stats + 256, n);
    bn_finalize<<<1, 128>>>(stats + 256, g2, be2, scsh, n);

    // ---- pool (BN+ReLU fused) + classifier ----
    counts_kernel<<<64, 256>>>(batch, counts, n);
    pool_kernel<<<(n + 127) / 128, 128>>>(bufC, scsh, batch, pooled, n);
    classifier_kernel<<<1, 256>>>(pooled, counts, Wc1, bc1, Wc2, bc2, out);
}

// round 12
// speedup vs baseline: 1.1425x; 1.1425x over previous
#include <cuda_runtime.h>
#include <cuda_bf16.h>
#include <mma.h>
#include <cstdint>

using namespace nvcuda;

#define NNODES 100000
#define NEDGES 1600000
#define HID 128
#define NGRAPH 64
#define SCAN_BLK 1024
#define EPW 16           // edges per warp (two batches of 8)

#define LDA 36           // padded A tile stride (floats)
#define LDW 132          // padded W / C tile stride (floats)

// ---------------- scratch (device globals) -----------------------------------
__device__ uint2  g_ybf[NNODES * 32];          // y in bf16: 128 bf16/row = 32 uint2
__device__ float4 g_bufB4[NNODES * HID / 4];   // agg layer 1
__device__ float4 g_bufC4[NNODES * HID / 4];   // agg layer 2
__device__ int    g_indeg[NNODES];
__device__ int    g_btot[128];
__device__ int    g_cursor[NNODES];
__device__ int2   g_edges[NEDGES];             // (src,dst) sorted by dst
__device__ float  g_stats[4 * HID];            // layer1: [0,256), layer2: [256,512)
__device__ float  g_scsh[2 * HID];
__device__ float  g_pooled[NGRAPH * HID];
__device__ float  g_counts[NGRAPH];

// ---------------- fused zero init ---------------------------------------------
__global__ void zero_all(int* indeg, float* stats, float* pooled, float* counts, int n) {
    int i = blockIdx.x * blockDim.x + threadIdx.x;
    if (i < n) indeg[i] = 0;
    if (i < 4 * HID) stats[i] = 0.f;
    if (i < NGRAPH * HID) pooled[i] = 0.f;
    if (i < NGRAPH) counts[i] = 0.f;
}

__global__ void indeg_count(const int* __restrict__ dst, int* indeg, int E) {
    int e = blockIdx.x * blockDim.x + threadIdx.x;
    if (e < E) atomicAdd(&indeg[dst[e]], 1);
}

__global__ void block_totals(const int* __restrict__ indeg, int* btot, int n) {
    __shared__ int sh[SCAN_BLK];
    int i = blockIdx.x * SCAN_BLK + threadIdx.x;
    sh[threadIdx.x] = (i < n) ? indeg[i] : 0;
    __syncthreads();
    for (int s = SCAN_BLK / 2; s > 0; s >>= 1) {
        if (threadIdx.x < s) sh[threadIdx.x] += sh[threadIdx.x + s];
        __syncthreads();
    }
    if (threadIdx.x == 0) btot[blockIdx.x] = sh[0];
}

// scan within block + per-block offset reduced from btot (scan_tops fused in)
__global__ void scan_blocks(const int* __restrict__ indeg, const int* __restrict__ btot,
                            int* cursor, int n, int nb) {
    __shared__ int sh[SCAN_BLK];
    __shared__ int off_sh[128];
    int tid = threadIdx.x;
    int i = blockIdx.x * SCAN_BLK + tid;
    int v = (i < n) ? indeg[i] : 0;
    sh[tid] = v;
    if (tid < 128) off_sh[tid] = (tid < blockIdx.x && tid < nb) ? btot[tid] : 0;
    __syncthreads();
    for (int off = 1; off < SCAN_BLK; off <<= 1) {
        int t = (tid >= off) ? sh[tid - off] : 0;
        __syncthreads();
        sh[tid] += t;
        __syncthreads();
    }
    // reduce off_sh (128 -> 1)
    for (int s = 64; s > 0; s >>= 1) {
        if (tid < s) off_sh[tid] += off_sh[tid + s];
        __syncthreads();
    }
    if (i < n) cursor[i] = off_sh[0] + sh[tid] - v;  // exclusive prefix
}

__global__ void sort_fill(const int* __restrict__ src, const int* __restrict__ dst,
                          int* cursor, int2* edges, int E) {
    int e = blockIdx.x * blockDim.x + threadIdx.x;
    if (e < E) {
        int d = dst[e];
        int pos = atomicAdd(&cursor[d], 1);
        edges[pos] = make_int2(src[e], d);
    }
}

// ---------------- fused GEMM (tf32 tensor cores, padded smem) -------------------
// ybf[row] = bf16((f(A)[row] @ W) * dinv);  agg[row] = same * dinv  (fp32)
// f = nan_to_num (mode 1) / BN+ReLU via scsh (mode 2)
// 8 warps: warp = (row_blk 0..3) x16 rows, (col_blk 0..1) x64 cols, wmma m16n16k8.
__global__ __launch_bounds__(256) void gemm128(
    const float* __restrict__ A, const float* __restrict__ W,
    const float* __restrict__ scsh, const int* __restrict__ indeg,
    uint2* __restrict__ ybf, float* __restrict__ agg, int n, int mode)
{
    // As: 64 x LDA(36) = 2304 | Ws: 32 x LDW(132) = 4224 | C stash: 64 x 132 = 8448
    __shared__ __align__(16) float smem[64 * LDW];
    float* As = smem;              // 64 x 36
    float* Ws = smem + 64 * LDA;   // 32 x 132

    int r0 = blockIdx.x * 64;
    int tid = threadIdx.x;
    int warp = tid >> 5;
    int row_blk = warp & 3;        // x16 rows
    int col_blk = warp >> 2;       // x64 cols

    wmma::fragment<wmma::accumulator, 16, 16, 8, float> acc[4];
    #pragma unroll
    for (int c = 0; c < 4; c++) wmma::fill_fragment(acc[c], 0.f);

    for (int kc = 0; kc < 4; kc++) {
        // A tile 64x32 with transform, converted to tf32 (padded rows)
        #pragma unroll
        for (int t = 0; t < 2; t++) {
            int i = tid + t * 256;
            int r = i >> 3;
            int k4 = (i & 7) * 4;
            float4 v = make_float4(0.f, 0.f, 0.f, 0.f);
            if (r0 + r < n)
                v = *(const float4*)(A + (size_t)(r0 + r) * 128 + kc * 32 + k4);
            if (mode == 1) {
                v.x = (v.x == v.x) ? v.x : 0.f;
                v.y = (v.y == v.y) ? v.y : 0.f;
                v.z = (v.z == v.z) ? v.z : 0.f;
                v.w = (v.w == v.w) ? v.w : 0.f;
            } else if (mode == 2) {
                int c = kc * 32 + k4;
                v.x = fmaxf(v.x * scsh[c + 0] + scsh[128 + c + 0], 0.f);
                v.y = fmaxf(v.y * scsh[c + 1] + scsh[128 + c + 1], 0.f);
                v.z = fmaxf(v.z * scsh[c + 2] + scsh[128 + c + 2], 0.f);
                v.w = fmaxf(v.w * scsh[c + 3] + scsh[128 + c + 3], 0.f);
            }
            v.x = wmma::__float_to_tf32(v.x);
            v.y = wmma::__float_to_tf32(v.y);
            v.z = wmma::__float_to_tf32(v.z);
            v.w = wmma::__float_to_tf32(v.w);
            *(float4*)(As + r * LDA + k4) = v;
        }
        // W tile 32x128, converted to tf32 (padded rows)
        #pragma unroll
        for (int t = 0; t < 4; t++) {
            int i = tid + t * 256;
            int k = i >> 5, c4 = (i & 31) * 4;
            float4 w = *(const float4*)(W + (size_t)(kc * 32 + k) * 128 + c4);
            w.x = wmma::__float_to_tf32(w.x);
            w.y = wmma::__float_to_tf32(w.y);
            w.z = wmma::__float_to_tf32(w.z);
            w.w = wmma::__float_to_tf32(w.w);
            *(float4*)(Ws + k * LDW + c4) = w;
        }
        __syncthreads();

        #pragma unroll
        for (int kk = 0; kk < 4; kk++) {
            wmma::fragment<wmma::matrix_a, 16, 16, 8, wmma::precision::tf32, wmma::row_major> af;
            wmma::load_matrix_sync(af, As + (row_blk * 16) * LDA + kk * 8, LDA);
            #pragma unroll
            for (int c = 0; c < 4; c++) {
                wmma::fragment<wmma::matrix_b, 16, 16, 8, wmma::precision::tf32, wmma::row_major> bf;
                wmma::load_matrix_sync(bf, Ws + (kk * 8) * LDW + col_blk * 64 + c * 16, LDW);
                wmma::mma_sync(acc[c], af, bf, acc[c]);
            }
        }
        __syncthreads();
    }

    // stash accumulators into smem with padded stride (As/Ws dead now)
    #pragma unroll
    for (int c = 0; c < 4; c++)
        wmma::store_matrix_sync(smem + (row_blk * 16) * LDW + col_blk * 64 + c * 16,
                                acc[c], LDW, wmma::mem_row_major);
    __syncthreads();

    // epilogue
    int cg = tid & 31;
    int rg = tid >> 5;
    #pragma unroll
    for (int r = 0; r < 8; r++) {
        int row = r0 + rg * 8 + r;
        if (row < n) {
            float di = rsqrtf((float)indeg[row] + 1.0f);
            float4 v = *(float4*)(smem + (rg * 8 + r) * LDW + cg * 4);
            v.x *= di; v.y *= di; v.z *= di; v.w *= di;
            __nv_bfloat162 h0 = __floats2bfloat162_rn(v.x, v.y);
            __nv_bfloat162 h1 = __floats2bfloat162_rn(v.z, v.w);
            uint2 u;
            u.x = *(unsigned int*)&h0;
            u.y = *(unsigned int*)&h1;
            ybf[(size_t)row * 32 + cg] = u;
            float4 s = make_float4(v.x * di, v.y * di, v.z * di, v.w * di);
            *(float4*)(agg + (size_t)row * 128 + cg * 4) = s;
        }
    }
}

// ---------------- sorted edge scatter (bf16 reads, fp32 accumulate) ------------
__device__ __forceinline__ void red_flush(float* agg, const int* indeg,
                                          int node, int lane, float4 a)
{
    float c = rsqrtf((float)__ldg(indeg + node) + 1.0f);
    float* p = agg + (size_t)node * 128 + lane * 4;
    asm volatile("red.global.add.v4.f32 [%0], {%1, %2, %3, %4};"
                 :: "l"(p), "f"(a.x * c), "f"(a.y * c), "f"(a.z * c), "f"(a.w * c)
                 : "memory");
}

__device__ __forceinline__ float4 unpack_bf16x4(uint2 u) {
    __nv_bfloat162 h0 = *(__nv_bfloat162*)&u.x;
    __nv_bfloat162 h1 = *(__nv_bfloat162*)&u.y;
    float2 a = __bfloat1622float2(h0);
    float2 b = __bfloat1622float2(h1);
    return make_float4(a.x, a.y, b.x, b.y);
}

__global__ __launch_bounds__(256) void edge_scatter_sorted(
    const uint2* __restrict__ ybf, const int2* __restrict__ edges,
    const int* __restrict__ indeg, float* __restrict__ agg, int E)
{
    int lane = threadIdx.x & 31;
    int warp = blockIdx.x * 8 + (threadIdx.x >> 5);
    int e0 = warp * EPW;
    if (e0 >= E) return;

    if (e0 + EPW <= E) {
        float4 acc = make_float4(0.f, 0.f, 0.f, 0.f);
        int cur = -1;
        #pragma unroll
        for (int b = 0; b < EPW / 8; b++) {
            int2 ed[8];
            #pragma unroll
            for (int j = 0; j < 8; j++)
                ed[j] = __ldg(edges + e0 + b * 8 + j);
            uint2 raw[8];
            #pragma unroll
            for (int j = 0; j < 8; j++)
                raw[j] = __ldg(ybf + (size_t)ed[j].x * 32 + lane);
            #pragma unroll
            for (int j = 0; j < 8; j++) {
                float4 v = unpack_bf16x4(raw[j]);
                if (ed[j].y == cur) {              // warp-uniform branch
                    acc.x += v.x; acc.y += v.y;
                    acc.z += v.z; acc.w += v.w;
                } else {
                    if (cur >= 0) red_flush(agg, indeg, cur, lane, acc);
                    cur = ed[j].y;
                    acc = v;
                }
            }
        }
        red_flush(agg, indeg, cur, lane, acc);
    } else {
        for (int e = e0; e < E; e++) {
            int2 ed = __ldg(edges + e);
            float4 v = unpack_bf16x4(__ldg(ybf + (size_t)ed.x * 32 + lane));
            red_flush(agg, indeg, ed.y, lane, v);
        }
    }
}

// ---------------- batchnorm -----------------------------------------------------
__global__ __launch_bounds__(128) void bn_stats(
    const float* __restrict__ src, float* __restrict__ stats, int n)
{
    int col = threadIdx.x;
    float s = 0.f, s2 = 0.f;
    for (int r = blockIdx.x; r < n; r += gridDim.x) {
        float v = src[(size_t)r * 128 + col];
        s += v; s2 += v * v;
    }
    atomicAdd(&stats[col], s);
    atomicAdd(&stats[128 + col], s2);
}

__global__ void bn_finalize(
    const float* __restrict__ stats, const float* __restrict__ gamma,
    const float* __restrict__ beta, float* __restrict__ scsh, int n)
{
    int c = threadIdx.x;  // 128 threads
    float invn = 1.0f / (float)n;
    float mean = stats[c] * invn;
    float var  = stats[128 + c] * invn - mean * mean;
    float sc = rsqrtf(var + 1e-5f) * gamma[c];
    scsh[c] = sc;
    scsh[128 + c] = beta[c] - mean * sc;
}

// ---------------- pooling (BN+ReLU fused; batch sorted) --------------------------
__global__ __launch_bounds__(256) void counts_kernel(
    const int* __restrict__ batch, float* __restrict__ counts, int n)
{
    __shared__ float sc[NGRAPH];
    if (threadIdx.x < NGRAPH) sc[threadIdx.x] = 0.f;
    __syncthreads();
    for (int i = blockIdx.x * blockDim.x + threadIdx.x; i < n; i += gridDim.x * blockDim.x)
        atomicAdd(&sc[batch[i]], 1.0f);
    __syncthreads();
    if (threadIdx.x < NGRAPH) atomicAdd(&counts[threadIdx.x], sc[threadIdx.x]);
}

__global__ __launch_bounds__(128) void pool_kernel(
    const float* __restrict__ agg, const float* __restrict__ scsh,
    const int* __restrict__ batch, float* __restrict__ pooled, int n)
{
    int col = threadIdx.x;
    float sc = scsh[col], sh = scsh[128 + col];
    int r0 = blockIdx.x * 128;
    if (r0 >= n) return;
    int r1 = min(r0 + 128, n);
    int cg = batch[r0];
    float acc = 0.f;
    for (int r = r0; r < r1; r++) {
        int g = batch[r];
        if (g != cg) {
            atomicAdd(&pooled[cg * 128 + col], acc);
            acc = 0.f;
            cg = g;
        }
        acc += fmaxf(agg[(size_t)r * 128 + col] * sc + sh, 0.f);
    }
    atomicAdd(&pooled[cg * 128 + col], acc);
}

// ---------------- classifier (single block) --------------------------------------
__global__ __launch_bounds__(256) void classifier_kernel(
    const float* __restrict__ pooled, const float* __restrict__ counts,
    const float* __restrict__ Wc1, const float* __restrict__ bc1,
    const float* __restrict__ Wc2, const float* __restrict__ bc2,
    float* __restrict__ out)
{
    __shared__ float Z[64 * 64];
    __shared__ float inv[NGRAPH];
    int tid = threadIdx.x;
    if (tid < NGRAPH) inv[tid] = 1.0f / fmaxf(counts[tid], 1.0f);
    __syncthreads();

    for (int idx = tid; idx < 64 * 64; idx += 256) {
        int r = idx >> 6, c = idx & 63;
        float dot = 0.f;
        #pragma unroll 8
        for (int k = 0; k < 128; k++)
            dot += pooled[r * 128 + k] * Wc1[k * 64 + c];
        Z[idx] = fmaxf(dot * inv[r] + bc1[c], 0.f);
    }
    __syncthreads();

    for (int idx = tid; idx < 128; idx += 256) {
        int r = idx >> 1, c = idx & 1;
        float dot = bc2[c];
        #pragma unroll
        for (int k = 0; k < 64; k++)
            dot += Z[r * 64 + k] * Wc2[k * 2 + c];
        out[idx] = (dot == dot) ? dot : 0.f;  // nan_to_num
    }
}

// ---------------- launch -----------------------------------------------------------
extern "C" void kernel_launch(void* const* d_in, const int* in_sizes, int n_in,
                              void* d_out, int out_size)
{
    const float* x     = (const float*)d_in[0];
    const int*   ei    = (const int*)d_in[1];
    const int*   batch = (const int*)d_in[2];
    const float* W1  = (const float*)d_in[3];
    // b1 = d_in[4] — exactly cancelled by BatchNorm
    const float* g1  = (const float*)d_in[5];
    const float* be1 = (const float*)d_in[6];
    const float* W2  = (const float*)d_in[7];
    // b2 = d_in[8] — same
    const float* g2  = (const float*)d_in[9];
    const float* be2 = (const float*)d_in[10];
    const float* Wc1 = (const float*)d_in[11];
    const float* bc1 = (const float*)d_in[12];
    const float* Wc2 = (const float*)d_in[13];
    const float* bc2 = (const float*)d_in[14];
    float* out = (float*)d_out;

    int n = in_sizes[0] / HID;
    int E = in_sizes[1] / 2;
    const int* srcp = ei;
    const int* dstp = ei + E;

    float *bufB, *bufC, *stats, *scsh, *pooled, *counts;
    int *indeg, *btot, *cursor;
    int2 *edges;
    uint2 *ybf;
    cudaGetSymbolAddress((void**)&ybf,    g_ybf);
    cudaGetSymbolAddress((void**)&bufB,   g_bufB4);
    cudaGetSymbolAddress((void**)&bufC,   g_bufC4);
    cudaGetSymbolAddress((void**)&indeg,  g_indeg);
    cudaGetSymbolAddress((void**)&btot,   g_btot);
    cudaGetSymbolAddress((void**)&cursor, g_cursor);
    cudaGetSymbolAddress((void**)&edges,  g_edges);
    cudaGetSymbolAddress((void**)&stats,  g_stats);
    cudaGetSymbolAddress((void**)&scsh,   g_scsh);
    cudaGetSymbolAddress((void**)&pooled, g_pooled);
    cudaGetSymbolAddress((void**)&counts, g_counts);

    int nb256 = (n + 255) / 256;
    int eb256 = (E + 255) / 256;
    int gemm_blocks = (n + 63) / 64;
    int scan_nb = (n + SCAN_BLK - 1) / SCAN_BLK;
    int scat_blocks = (E + 8 * EPW - 1) / (8 * EPW);

    // (1) fused zero init; (2) degree count; (3) scan part 1
    zero_all<<<nb256, 256>>>(indeg, stats, pooled, counts, n);
    indeg_count<<<eb256, 256>>>(dstp, indeg, E);
    block_totals<<<scan_nb, SCAN_BLK>>>(indeg, btot, n);

    // (4) layer-1 GEMM — the launch ncu captures
    gemm128<<<gemm_blocks, 256>>>(x, W1, scsh, indeg, ybf, bufB, n, 1);

    // (5)(6) finish dst-sorted edge list before scatter (scan_tops fused in)
    scan_blocks<<<scan_nb, SCAN_BLK>>>(indeg, btot, cursor, n, scan_nb);
    sort_fill<<<eb256, 256>>>(srcp, dstp, cursor, edges, E);

    // ---- layer 1 aggregation + BN ----
    edge_scatter_sorted<<<scat_blocks, 256>>>(ybf, edges, indeg, bufB, E);
    bn_stats<<<512, 128>>>(bufB, stats, n);
    bn_finalize<<<1, 128>>>(stats, g1, be1, scsh, n);

    // ---- layer 2 ----
    gemm128<<<gemm_blocks, 256>>>(bufB, W2, scsh, indeg, ybf, bufC, n, 2);
    edge_scatter_sorted<<<scat_blocks, 256>>>(ybf, edges, indeg, bufC, E);
    bn_stats<<<512, 128>>>(bufC, stats + 256, n);
    bn_finalize<<<1, 128>>>(stats + 256, g2, be2, scsh, n);

    // ---- pool (BN+ReLU fused) + classifier ----
    counts_kernel<<<64, 256>>>(batch, counts, n);
    pool_kernel<<<(n + 127) / 128, 128>>>(bufC, scsh, batch, pooled, n);
    classifier_kernel<<<1, 256>>>(pooled, counts, Wc1, bc1, Wc2, bc2, out);
}

// round 13
// speedup vs baseline: 1.1701x; 1.0241x over previous
#include <cuda_runtime.h>
#include <cuda_bf16.h>
#include <mma.h>
#include <cstdint>

using namespace nvcuda;

#define NNODES 100000
#define NEDGES 1600000
#define HID 128
#define NGRAPH 64
#define SCAN_BLK 1024
#define EPW 16           // edges per warp (two batches of 8)

#define LDA 36           // padded A tile stride (floats)
#define LDW 132          // padded W / C tile stride (floats)

// ---------------- scratch (device globals) -----------------------------------
__device__ uint2  g_ybf[NNODES * 32];          // y in bf16: 128 bf16/row = 32 uint2
__device__ float4 g_bufB4[NNODES * HID / 4];   // agg layer 1
__device__ float4 g_bufC4[NNODES * HID / 4];   // agg layer 2
__device__ int    g_indeg[NNODES];
__device__ int    g_btot[128];
__device__ int    g_cursor[NNODES];
__device__ int2   g_edges[NEDGES];             // (src,dst) sorted by dst
__device__ float  g_stats[4 * HID];            // layer1: [0,256), layer2: [256,512)
__device__ float  g_scsh[2 * HID];
__device__ float  g_pooled[NGRAPH * HID];
__device__ float  g_counts[NGRAPH];

// ---------------- fused zero init ---------------------------------------------
__global__ void zero_all(int* indeg, float* stats, float* pooled, float* counts, int n) {
    int i = blockIdx.x * blockDim.x + threadIdx.x;
    if (i < n) indeg[i] = 0;
    if (i < 4 * HID) stats[i] = 0.f;
    if (i < NGRAPH * HID) pooled[i] = 0.f;
    if (i < NGRAPH) counts[i] = 0.f;
}

__global__ void indeg_count(const int* __restrict__ dst, int* indeg, int E) {
    int e = blockIdx.x * blockDim.x + threadIdx.x;
    if (e < E) atomicAdd(&indeg[dst[e]], 1);
}

__global__ void block_totals(const int* __restrict__ indeg, int* btot, int n) {
    __shared__ int sh[SCAN_BLK];
    int i = blockIdx.x * SCAN_BLK + threadIdx.x;
    sh[threadIdx.x] = (i < n) ? indeg[i] : 0;
    __syncthreads();
    for (int s = SCAN_BLK / 2; s > 0; s >>= 1) {
        if (threadIdx.x < s) sh[threadIdx.x] += sh[threadIdx.x + s];
        __syncthreads();
    }
    if (threadIdx.x == 0) btot[blockIdx.x] = sh[0];
}

// scan within block + per-block offset reduced from btot (scan_tops fused in)
__global__ void scan_blocks(const int* __restrict__ indeg, const int* __restrict__ btot,
                            int* cursor, int n, int nb) {
    __shared__ int sh[SCAN_BLK];
    __shared__ int off_sh[128];
    int tid = threadIdx.x;
    int i = blockIdx.x * SCAN_BLK + tid;
    int v = (i < n) ? indeg[i] : 0;
    sh[tid] = v;
    if (tid < 128) off_sh[tid] = (tid < blockIdx.x && tid < nb) ? btot[tid] : 0;
    __syncthreads();
    for (int off = 1; off < SCAN_BLK; off <<= 1) {
        int t = (tid >= off) ? sh[tid - off] : 0;
        __syncthreads();
        sh[tid] += t;
        __syncthreads();
    }
    for (int s = 64; s > 0; s >>= 1) {
        if (tid < s) off_sh[tid] += off_sh[tid + s];
        __syncthreads();
    }
    if (i < n) cursor[i] = off_sh[0] + sh[tid] - v;  // exclusive prefix
}

__global__ void sort_fill(const int* __restrict__ src, const int* __restrict__ dst,
                          int* cursor, int2* edges, int E) {
    int e = blockIdx.x * blockDim.x + threadIdx.x;
    if (e < E) {
        int d = dst[e];
        int pos = atomicAdd(&cursor[d], 1);
        edges[pos] = make_int2(src[e], d);
    }
}

// ---------------- fused GEMM (tf32 tensor cores, padded smem) -------------------
__global__ __launch_bounds__(256) void gemm128(
    const float* __restrict__ A, const float* __restrict__ W,
    const float* __restrict__ scsh, const int* __restrict__ indeg,
    uint2* __restrict__ ybf, float* __restrict__ agg, int n, int mode)
{
    __shared__ __align__(16) float smem[64 * LDW];
    float* As = smem;              // 64 x LDA
    float* Ws = smem + 64 * LDA;   // 32 x LDW

    int r0 = blockIdx.x * 64;
    int tid = threadIdx.x;
    int warp = tid >> 5;
    int row_blk = warp & 3;        // x16 rows
    int col_blk = warp >> 2;       // x64 cols

    wmma::fragment<wmma::accumulator, 16, 16, 8, float> acc[4];
    #pragma unroll
    for (int c = 0; c < 4; c++) wmma::fill_fragment(acc[c], 0.f);

    for (int kc = 0; kc < 4; kc++) {
        #pragma unroll
        for (int t = 0; t < 2; t++) {
            int i = tid + t * 256;
            int r = i >> 3;
            int k4 = (i & 7) * 4;
            float4 v = make_float4(0.f, 0.f, 0.f, 0.f);
            if (r0 + r < n)
                v = *(const float4*)(A + (size_t)(r0 + r) * 128 + kc * 32 + k4);
            if (mode == 1) {
                v.x = (v.x == v.x) ? v.x : 0.f;
                v.y = (v.y == v.y) ? v.y : 0.f;
                v.z = (v.z == v.z) ? v.z : 0.f;
                v.w = (v.w == v.w) ? v.w : 0.f;
            } else if (mode == 2) {
                int c = kc * 32 + k4;
                v.x = fmaxf(v.x * scsh[c + 0] + scsh[128 + c + 0], 0.f);
                v.y = fmaxf(v.y * scsh[c + 1] + scsh[128 + c + 1], 0.f);
                v.z = fmaxf(v.z * scsh[c + 2] + scsh[128 + c + 2], 0.f);
                v.w = fmaxf(v.w * scsh[c + 3] + scsh[128 + c + 3], 0.f);
            }
            v.x = wmma::__float_to_tf32(v.x);
            v.y = wmma::__float_to_tf32(v.y);
            v.z = wmma::__float_to_tf32(v.z);
            v.w = wmma::__float_to_tf32(v.w);
            *(float4*)(As + r * LDA + k4) = v;
        }
        #pragma unroll
        for (int t = 0; t < 4; t++) {
            int i = tid + t * 256;
            int k = i >> 5, c4 = (i & 31) * 4;
            float4 w = *(const float4*)(W + (size_t)(kc * 32 + k) * 128 + c4);
            w.x = wmma::__float_to_tf32(w.x);
            w.y = wmma::__float_to_tf32(w.y);
            w.z = wmma::__float_to_tf32(w.z);
            w.w = wmma::__float_to_tf32(w.w);
            *(float4*)(Ws + k * LDW + c4) = w;
        }
        __syncthreads();

        #pragma unroll
        for (int kk = 0; kk < 4; kk++) {
            wmma::fragment<wmma::matrix_a, 16, 16, 8, wmma::precision::tf32, wmma::row_major> af;
            wmma::load_matrix_sync(af, As + (row_blk * 16) * LDA + kk * 8, LDA);
            #pragma unroll
            for (int c = 0; c < 4; c++) {
                wmma::fragment<wmma::matrix_b, 16, 16, 8, wmma::precision::tf32, wmma::row_major> bf;
                wmma::load_matrix_sync(bf, Ws + (kk * 8) * LDW + col_blk * 64 + c * 16, LDW);
                wmma::mma_sync(acc[c], af, bf, acc[c]);
            }
        }
        __syncthreads();
    }

    #pragma unroll
    for (int c = 0; c < 4; c++)
        wmma::store_matrix_sync(smem + (row_blk * 16) * LDW + col_blk * 64 + c * 16,
                                acc[c], LDW, wmma::mem_row_major);
    __syncthreads();

    int cg = tid & 31;
    int rg = tid >> 5;
    #pragma unroll
    for (int r = 0; r < 8; r++) {
        int row = r0 + rg * 8 + r;
        if (row < n) {
            float di = rsqrtf((float)indeg[row] + 1.0f);
            float4 v = *(float4*)(smem + (rg * 8 + r) * LDW + cg * 4);
            v.x *= di; v.y *= di; v.z *= di; v.w *= di;
            __nv_bfloat162 h0 = __floats2bfloat162_rn(v.x, v.y);
            __nv_bfloat162 h1 = __floats2bfloat162_rn(v.z, v.w);
            uint2 u;
            u.x = *(unsigned int*)&h0;
            u.y = *(unsigned int*)&h1;
            ybf[(size_t)row * 32 + cg] = u;
            float4 s = make_float4(v.x * di, v.y * di, v.z * di, v.w * di);
            *(float4*)(agg + (size_t)row * 128 + cg * 4) = s;
        }
    }
}

// ---------------- sorted edge scatter (bf16 reads, fp32 accumulate) ------------
__device__ __forceinline__ void red_flush(float* agg, const int* indeg,
                                          int node, int lane, float4 a)
{
    float c = rsqrtf((float)__ldg(indeg + node) + 1.0f);
    float* p = agg + (size_t)node * 128 + lane * 4;
    asm volatile("red.global.add.v4.f32 [%0], {%1, %2, %3, %4};"
                 :: "l"(p), "f"(a.x * c), "f"(a.y * c), "f"(a.z * c), "f"(a.w * c)
                 : "memory");
}

__device__ __forceinline__ float4 unpack_bf16x4(uint2 u) {
    __nv_bfloat162 h0 = *(__nv_bfloat162*)&u.x;
    __nv_bfloat162 h1 = *(__nv_bfloat162*)&u.y;
    float2 a = __bfloat1622float2(h0);
    float2 b = __bfloat1622float2(h1);
    return make_float4(a.x, a.y, b.x, b.y);
}

__global__ __launch_bounds__(256) void edge_scatter_sorted(
    const uint2* __restrict__ ybf, const int2* __restrict__ edges,
    const int* __restrict__ indeg, float* __restrict__ agg, int E)
{
    int lane = threadIdx.x & 31;
    int warp = blockIdx.x * 8 + (threadIdx.x >> 5);
    int e0 = warp * EPW;
    if (e0 >= E) return;

    if (e0 + EPW <= E) {
        float4 acc = make_float4(0.f, 0.f, 0.f, 0.f);
        int cur = -1;
        #pragma unroll
        for (int b = 0; b < EPW / 8; b++) {
            int2 ed[8];
            #pragma unroll
            for (int j = 0; j < 8; j++)
                ed[j] = __ldg(edges + e0 + b * 8 + j);
            uint2 raw[8];
            #pragma unroll
            for (int j = 0; j < 8; j++)
                raw[j] = __ldg(ybf + (size_t)ed[j].x * 32 + lane);
            #pragma unroll
            for (int j = 0; j < 8; j++) {
                float4 v = unpack_bf16x4(raw[j]);
                if (ed[j].y == cur) {              // warp-uniform branch
                    acc.x += v.x; acc.y += v.y;
                    acc.z += v.z; acc.w += v.w;
                } else {
                    if (cur >= 0) red_flush(agg, indeg, cur, lane, acc);
                    cur = ed[j].y;
                    acc = v;
                }
            }
        }
        red_flush(agg, indeg, cur, lane, acc);
    } else {
        for (int e = e0; e < E; e++) {
            int2 ed = __ldg(edges + e);
            float4 v = unpack_bf16x4(__ldg(ybf + (size_t)ed.x * 32 + lane));
            red_flush(agg, indeg, ed.y, lane, v);
        }
    }
}

// ---------------- batchnorm -----------------------------------------------------
__global__ __launch_bounds__(128) void bn_stats(
    const float* __restrict__ src, float* __restrict__ stats, int n)
{
    int col = threadIdx.x;
    float s = 0.f, s2 = 0.f;
    for (int r = blockIdx.x; r < n; r += gridDim.x) {
        float v = src[(size_t)r * 128 + col];
        s += v; s2 += v * v;
    }
    atomicAdd(&stats[col], s);
    atomicAdd(&stats[128 + col], s2);
}

__global__ void bn_finalize(
    const float* __restrict__ stats, const float* __restrict__ gamma,
    const float* __restrict__ beta, float* __restrict__ scsh, int n)
{
    int c = threadIdx.x;  // 128 threads
    float invn = 1.0f / (float)n;
    float mean = stats[c] * invn;
    float var  = stats[128 + c] * invn - mean * mean;
    float sc = rsqrtf(var + 1e-5f) * gamma[c];
    scsh[c] = sc;
    scsh[128 + c] = beta[c] - mean * sc;
}

// ---------------- pooling (BN+ReLU fused; batch sorted) --------------------------
__global__ __launch_bounds__(256) void counts_kernel(
    const int* __restrict__ batch, float* __restrict__ counts, int n)
{
    __shared__ float sc[NGRAPH];
    if (threadIdx.x < NGRAPH) sc[threadIdx.x] = 0.f;
    __syncthreads();
    for (int i = blockIdx.x * blockDim.x + threadIdx.x; i < n; i += gridDim.x * blockDim.x)
        atomicAdd(&sc[batch[i]], 1.0f);
    __syncthreads();
    if (threadIdx.x < NGRAPH) atomicAdd(&counts[threadIdx.x], sc[threadIdx.x]);
}

__global__ __launch_bounds__(128) void pool_kernel(
    const float* __restrict__ agg, const float* __restrict__ scsh,
    const int* __restrict__ batch, float* __restrict__ pooled, int n)
{
    int col = threadIdx.x;
    float sc = scsh[col], sh = scsh[128 + col];
    int r0 = blockIdx.x * 128;
    if (r0 >= n) return;
    int r1 = min(r0 + 128, n);
    int cg = batch[r0];
    float acc = 0.f;
    for (int r = r0; r < r1; r++) {
        int g = batch[r];
        if (g != cg) {
            atomicAdd(&pooled[cg * 128 + col], acc);
            acc = 0.f;
            cg = g;
        }
        acc += fmaxf(agg[(size_t)r * 128 + col] * sc + sh, 0.f);
    }
    atomicAdd(&pooled[cg * 128 + col], acc);
}

// ---------------- classifier (single block) --------------------------------------
__global__ __launch_bounds__(256) void classifier_kernel(
    const float* __restrict__ pooled, const float* __restrict__ counts,
    const float* __restrict__ Wc1, const float* __restrict__ bc1,
    const float* __restrict__ Wc2, const float* __restrict__ bc2,
    float* __restrict__ out)
{
    __shared__ float Z[64 * 64];
    __shared__ float inv[NGRAPH];
    int tid = threadIdx.x;
    if (tid < NGRAPH) inv[tid] = 1.0f / fmaxf(counts[tid], 1.0f);
    __syncthreads();

    for (int idx = tid; idx < 64 * 64; idx += 256) {
        int r = idx >> 6, c = idx & 63;
        float dot = 0.f;
        #pragma unroll 8
        for (int k = 0; k < 128; k++)
            dot += pooled[r * 128 + k] * Wc1[k * 64 + c];
        Z[idx] = fmaxf(dot * inv[r] + bc1[c], 0.f);
    }
    __syncthreads();

    for (int idx = tid; idx < 128; idx += 256) {
        int r = idx >> 1, c = idx & 1;
        float dot = bc2[c];
        #pragma unroll
        for (int k = 0; k < 64; k++)
            dot += Z[r * 64 + k] * Wc2[k * 2 + c];
        out[idx] = (dot == dot) ? dot : 0.f;  // nan_to_num
    }
}

// ---------------- launch -----------------------------------------------------------
extern "C" void kernel_launch(void* const* d_in, const int* in_sizes, int n_in,
                              void* d_out, int out_size)
{
    const float* x     = (const float*)d_in[0];
    const int*   ei    = (const int*)d_in[1];
    const int*   batch = (const int*)d_in[2];
    const float* W1  = (const float*)d_in[3];
    // b1 = d_in[4] — exactly cancelled by BatchNorm
    const float* g1  = (const float*)d_in[5];
    const float* be1 = (const float*)d_in[6];
    const float* W2  = (const float*)d_in[7];
    // b2 = d_in[8] — same
    const float* g2  = (const float*)d_in[9];
    const float* be2 = (const float*)d_in[10];
    const float* Wc1 = (const float*)d_in[11];
    const float* bc1 = (const float*)d_in[12];
    const float* Wc2 = (const float*)d_in[13];
    const float* bc2 = (const float*)d_in[14];
    float* out = (float*)d_out;

    int n = in_sizes[0] / HID;
    int E = in_sizes[1] / 2;
    const int* srcp = ei;
    const int* dstp = ei + E;

    float *bufB, *bufC, *stats, *scsh, *pooled, *counts;
    int *indeg, *btot, *cursor;
    int2 *edges;
    uint2 *ybf;
    cudaGetSymbolAddress((void**)&ybf,    g_ybf);
    cudaGetSymbolAddress((void**)&bufB,   g_bufB4);
    cudaGetSymbolAddress((void**)&bufC,   g_bufC4);
    cudaGetSymbolAddress((void**)&indeg,  g_indeg);
    cudaGetSymbolAddress((void**)&btot,   g_btot);
    cudaGetSymbolAddress((void**)&cursor, g_cursor);
    cudaGetSymbolAddress((void**)&edges,  g_edges);
    cudaGetSymbolAddress((void**)&stats,  g_stats);
    cudaGetSymbolAddress((void**)&scsh,   g_scsh);
    cudaGetSymbolAddress((void**)&pooled, g_pooled);
    cudaGetSymbolAddress((void**)&counts, g_counts);

    int nb256 = (n + 255) / 256;
    int eb256 = (E + 255) / 256;
    int gemm_blocks = (n + 63) / 64;
    int scan_nb = (n + SCAN_BLK - 1) / SCAN_BLK;
    int scat_blocks = (E + 8 * EPW - 1) / (8 * EPW);

    // side stream + events for fork/join inside graph capture (created once;
    // host-side objects, no device memory)
    static cudaStream_t s2 = nullptr;
    static cudaEvent_t ev_fork = nullptr, ev_join = nullptr;
    if (!s2) {
        cudaStreamCreateWithFlags(&s2, cudaStreamNonBlocking);
        cudaEventCreateWithFlags(&ev_fork, cudaEventDisableTiming);
        cudaEventCreateWithFlags(&ev_join, cudaEventDisableTiming);
    }
    cudaStream_t s0 = 0;  // capture stream (legacy default joins capture)

    // main stream: init + degree count (gemm1 needs indeg)
    zero_all<<<nb256, 256, 0, s0>>>(indeg, stats, pooled, counts, n);
    indeg_count<<<eb256, 256, 0, s0>>>(dstp, indeg, E);

    // fork: side stream builds sorted edge list + counts, overlapping gemm1
    cudaEventRecord(ev_fork, s0);
    cudaStreamWaitEvent(s2, ev_fork, 0);
    block_totals<<<scan_nb, SCAN_BLK, 0, s2>>>(indeg, btot, n);
    scan_blocks<<<scan_nb, SCAN_BLK, 0, s2>>>(indeg, btot, cursor, n, scan_nb);
    sort_fill<<<eb256, 256, 0, s2>>>(srcp, dstp, cursor, edges, E);
    counts_kernel<<<64, 256, 0, s2>>>(batch, counts, n);
    cudaEventRecord(ev_join, s2);

    // main stream: layer-1 GEMM runs concurrently with the build
    gemm128<<<gemm_blocks, 256, 0, s0>>>(x, W1, scsh, indeg, ybf, bufB, n, 1);

    // join: scatter needs both gemm1 (ybf) and the edge list
    cudaStreamWaitEvent(s0, ev_join, 0);

    // ---- layer 1 aggregation + BN ----
    edge_scatter_sorted<<<scat_blocks, 256, 0, s0>>>(ybf, edges, indeg, bufB, E);
    bn_stats<<<512, 128, 0, s0>>>(bufB, stats, n);
    bn_finalize<<<1, 128, 0, s0>>>(stats, g1, be1, scsh, n);

    // ---- layer 2 ----
    gemm128<<<gemm_blocks, 256, 0, s0>>>(bufB, W2, scsh, indeg, ybf, bufC, n, 2);
    edge_scatter_sorted<<<scat_blocks, 256, 0, s0>>>(ybf, edges, indeg, bufC, E);
    bn_stats<<<512, 128, 0, s0>>>(bufC, stats + 256, n);
    bn_finalize<<<1, 128, 0, s0>>>(stats + 256, g2, be2, scsh, n);

    // ---- pool (BN+ReLU fused) + classifier ----
    pool_kernel<<<(n + 127) / 128, 128, 0, s0>>>(bufC, scsh, batch, pooled, n);
    classifier_kernel<<<1, 256, 0, s0>>>(pooled, counts, Wc1, bc1, Wc2, bc2, out);
}